// round 9
// baseline (speedup 1.0000x reference)
#include <cuda_runtime.h>

// Problem shape (fixed by the dataset reference)
#define BB      16
#define TT      256
#define NPTS    2048
#define NF      (NPTS * 3)             // 6144 flat (point,coord) indices
#define TCHUNK  32
#define NCHUNKS (TT / TCHUNK)          // 8
#define BC      (BB * NCHUNKS)         // 128 partial groups
#define THREADS 256
#define CPB     (NF / THREADS)         // 24 flat windows (CTAs per bc group)
#define NCTA    (BC * CPB)             // 3072 main CTAs
#define RFIN    256                    // finisher CTAs
#define PTSPC   (NPTS / RFIN)          // 8 points per finisher
#define FLATSPC (PTSPC * 3)            // 24 flats per finisher
#define NGRP    8                      // bc groups in finish stage A
#define BCG     (BC / NGRP)            // 16 bc per group
#define WINDOWS CPB                    // 24

// Partial per-(n,c) stats: g_part[bc][stat][flat], stat: 0 sxp, 1 ssp, 2 sxg, 3 ssg, 4 cnt
__device__ float  g_part[BC * 5 * NF];      // 15.7 MB, fully overwritten each replay
__device__ float4 g_pscal[NCTA];            // per-main-CTA: cnt3x, recon, vels, velc3x
__device__ float  g_fin[RFIN];              // per-finisher identity partial
__device__ unsigned g_wctr[WINDOWS];        // per-window completion counters (self-reset)
__device__ unsigned g_ctr;                  // finisher counter (self-reset)

__global__ __launch_bounds__(THREADS, 8) void fused_k(
    const float* __restrict__ pred,
    const float* __restrict__ gt,
    const float* __restrict__ vis,
    float* __restrict__ out)
{
    const int bid = blockIdx.x;
    const int tid = threadIdx.x;

    if (bid < NCTA) {
        // ================= producer: main streaming pass =================
        const int bc    = bid / CPB;
        const int sub   = bid - bc * CPB;          // flat window id
        const int flat  = sub * THREADS + tid;
        const int chunk = bc & (NCHUNKS - 1);
        const int b     = bc >> 3;                 // NCHUNKS = 8
        const int t0    = chunk * TCHUNK;

        const int   n = flat / 3;
        const int   c = flat - 3 * n;
        const float w = (c == 2) ? 2.f : 1.f;

        const int row0 = b * TT + t0;
        const float* pp = pred + (long)row0 * NF + flat;
        const float* gp = gt   + (long)row0 * NF + flat;
        const float* vp = vis  + (long)row0 * NPTS + n;

        float sxp = 0.f, ssp = 0.f, sxg = 0.f, ssg = 0.f, cnt = 0.f;
        float recon = 0.f, vels = 0.f, velc = 0.f;

        float pd = 0.f, pm = 0.f;
        if (t0 > 0) {
            pm = (vp[-NPTS] > 0.5f) ? 1.f : 0.f;
            pd = pp[-NF] - gp[-NF];
        }

#pragma unroll 4
        for (int t = 0; t < TCHUNK; ++t) {
            float m = (vp[0] > 0.5f) ? 1.f : 0.f;
            float p = pp[0];
            float g = gp[0];
            pp += NF; gp += NF; vp += NPTS;

            float d = p - g;
            recon += w * (m * d) * d;
            cnt   += m;

            float mp = m * p, mg = m * g;
            sxp += mp;  ssp += mp * p;
            sxg += mg;  ssg += mg * g;

            float vm = m * pm;
            float tv = d - pd;
            vels += (vm * tv) * tv;
            velc += vm;

            pd = d; pm = m;
        }

        // per-(n,c) stats -> partial buffer (coalesced stores, no atomics)
        {
            float* o = &g_part[(long)bc * 5 * NF + flat];
            o[0 * NF] = sxp;
            o[1 * NF] = ssp;
            o[2 * NF] = sxg;
            o[3 * NF] = ssg;
            o[4 * NF] = cnt;
        }

        // scalar partials: warp reduce -> smem -> one float4 store per CTA
        const unsigned fmask = 0xffffffffu;
        __shared__ float swarp[8][4];
#pragma unroll
        for (int o = 16; o > 0; o >>= 1) {
            cnt   += __shfl_down_sync(fmask, cnt,   o);
            recon += __shfl_down_sync(fmask, recon, o);
            vels  += __shfl_down_sync(fmask, vels,  o);
            velc  += __shfl_down_sync(fmask, velc,  o);
        }
        int wd = tid >> 5;
        if ((tid & 31) == 0) {
            swarp[wd][0] = cnt; swarp[wd][1] = recon; swarp[wd][2] = vels; swarp[wd][3] = velc;
        }
        __syncthreads();
        if (tid == 0) {
            float s0 = 0.f, s1 = 0.f, s2 = 0.f, s3 = 0.f;
#pragma unroll
            for (int i = 0; i < 8; ++i) {
                s0 += swarp[i][0]; s1 += swarp[i][1]; s2 += swarp[i][2]; s3 += swarp[i][3];
            }
            g_pscal[bid] = make_float4(s0, s1, s2, s3);
            __threadfence();                       // release partials + pscal
            atomicAdd(&g_wctr[sub], 1u);
        }
        return;
    }

    // ================= consumer: finisher CTA =================
    const int fx = bid - NCTA;                     // 0..255
    const int f0 = fx * FLATSPC;                   // first flat
    const int w0 = f0 >> 8;                        // windows of 256 flats
    const int w1 = (f0 + FLATSPC - 1) >> 8;

    __shared__ float sgrp[NGRP][5][FLATSPC];       // 960 floats
    __shared__ float scomb[5][FLATSPC];
    __shared__ bool  islast;

    // wait until every bc has written this finisher's flat span
    if (tid == 0) {
        volatile unsigned* wc = g_wctr;
        while (wc[w0] < BC) __nanosleep(128);
        while (wc[w1] < BC) __nanosleep(128);
    }
    __syncthreads();
    __threadfence();

    // Stage A: 240 threads -> grp = t/30, pair = t%30 (stat = pair/6, col = pair%6)
    if (tid < NGRP * 30) {
        int grp  = tid / 30;
        int pair = tid - grp * 30;
        int stat = pair / 6;
        int col  = pair - stat * 6;
        const float* base = g_part + (long)(grp * BCG) * 5 * NF
                                   + (long)stat * NF + f0 + col * 4;
        float4 s = make_float4(0.f, 0.f, 0.f, 0.f);
#pragma unroll
        for (int i = 0; i < BCG; ++i) {
            float4 v = __ldcg((const float4*)(base + (long)i * 5 * NF));
            s.x += v.x; s.y += v.y; s.z += v.z; s.w += v.w;
        }
        *(float4*)&sgrp[grp][stat][col * 4] = s;
    }
    __syncthreads();

    // Stage B1: combine groups (120 threads)
    if (tid < 5 * FLATSPC) {
        int stat = tid / FLATSPC;
        int fo   = tid - stat * FLATSPC;
        float s = 0.f;
#pragma unroll
        for (int g = 0; g < NGRP; ++g)
            s += sgrp[g][stat][fo];
        scomb[stat][fo] = s;
    }
    __syncthreads();

    // Stage B2: identity for this finisher's 8 points (threads 0..7 of warp 0)
    float idp = 0.f;
    if (tid < PTSPC) {
        int fo = tid * 3;
        float cn = scomb[4][fo];
        if (cn > 1.f) {
            float inv_n  = 1.f / cn;
            float inv_n1 = 1.f / (cn - 1.f);
            float adsum = 0.f, vgsum = 0.f;
#pragma unroll
            for (int k = 0; k < 3; ++k) {
                float sp  = scomb[0][fo + k];
                float ssp = scomb[1][fo + k];
                float sg  = scomb[2][fo + k];
                float ssg = scomb[3][fo + k];
                float vp = (ssp - sp * sp * inv_n) * inv_n1;
                float vg = (ssg - sg * sg * inv_n) * inv_n1;
                adsum += fabsf(vp - vg);
                vgsum += vg;
            }
            idp = adsum / (vgsum + 1e-6f);
        }
    }
    if (tid < 32) {
#pragma unroll
        for (int o = 16; o > 0; o >>= 1)
            idp += __shfl_down_sync(0xffffffffu, idp, o);
        if (tid == 0) g_fin[fx] = idp;
    }
    __threadfence();
    if (tid == 0) {
        unsigned old = atomicAdd(&g_ctr, 1u);
        islast = (old == RFIN - 1);
    }
    __syncthreads();

    if (islast) {
        __threadfence();
        __shared__ float red[5][RFIN];
        // identity partials + fold of all main-CTA scalar partials (12 per thread)
        {
            float a0 = __ldcg(&g_fin[tid]);
            float s0 = 0.f, s1 = 0.f, s2 = 0.f, s3 = 0.f;
#pragma unroll
            for (int i = 0; i < NCTA / RFIN; ++i) {     // 12
                float4 v = __ldcg(&g_pscal[tid * (NCTA / RFIN) + i]);
                s0 += v.x; s1 += v.y; s2 += v.z; s3 += v.w;
            }
            red[0][tid] = a0;
            red[1][tid] = s0; red[2][tid] = s1; red[3][tid] = s2; red[4][tid] = s3;
        }
        __syncthreads();
#pragma unroll
        for (int s = RFIN / 2; s > 0; s >>= 1) {
            if (tid < s) {
#pragma unroll
                for (int k = 0; k < 5; ++k)
                    red[k][tid] += red[k][tid + s];
            }
            __syncthreads();
        }

        if (tid == 0) {
            float identity = red[0][0] / (float)NPTS;
            // counts accumulated once per coord (3x per point) -> exact /3
            float nv = red[1][0] / 3.0f;
            float rs = red[2][0];
            float vs = red[3][0];
            float vc = red[4][0] / 3.0f;
            float recon    = (nv > 0.f) ? rs / fmaxf(nv, 1.f) : 0.f;
            float temporal = (vc > 0.f) ? vs / fmaxf(vc, 1.f) : 0.f;

            // adaptive re-weighting (faithful to reference)
            float rl = recon, tl = temporal, il = identity;
            bool  all_pos = (rl > 0.f) && (tl > 0.f) && (il > 0.f);
            float maxc    = fmaxf(rl, fmaxf(tl, il));
            float target  = maxc / 3.f;
            float thresh  = 10.f * target;
            float rw = (all_pos && rl > thresh) ? 1.0f * target / fmaxf(rl, 1e-30f) : 1.0f;
            float tw = (all_pos && tl > thresh) ? 0.5f * target / fmaxf(tl, 1e-30f) : 0.5f;
            float iw = (all_pos && il > thresh) ? 0.1f * target / fmaxf(il, 1e-30f) : 0.1f;

            out[0] = rw * recon + tw * temporal + iw * identity;
            out[1] = recon;
            out[2] = temporal;
            out[3] = identity;

            // self-reset all counters for the next graph replay
#pragma unroll
            for (int i = 0; i < WINDOWS; ++i) g_wctr[i] = 0u;
            g_ctr = 0u;
        }
    }
}

extern "C" void kernel_launch(void* const* d_in, const int* in_sizes, int n_in,
                              void* d_out, int out_size)
{
    const float* pred = (const float*)d_in[0];
    const float* gt   = (const float*)d_in[1];
    const float* vis  = (const float*)d_in[2];
    float* out = (float*)d_out;
    (void)in_sizes; (void)n_in; (void)out_size;

    fused_k<<<NCTA + RFIN, THREADS>>>(pred, gt, vis, out);   // single launch
}

// round 11
// speedup vs baseline: 1.0565x; 1.0565x over previous
#include <cuda_runtime.h>

// Problem shape (fixed by the dataset reference)
#define BB      16
#define TT      256
#define NPTS    2048
#define NF      (NPTS * 3)             // 6144 flat (point,coord) indices
#define TCHUNK  32
#define NCHUNKS (TT / TCHUNK)          // 8
#define BC      (BB * NCHUNKS)         // 128 partial groups
#define THREADS 256
#define WINDOWS (NF / THREADS)         // 24 flat windows
#define NITEMS  (BC * WINDOWS)         // 3072 work items
#define PCTA    1184                   // persistent CTAs (148 SM x 8)
#define RFIN    256                    // finisher CTAs (bid < RFIN)
#define PTSPC   (NPTS / RFIN)          // 8 points per finisher
#define FLATSPC (PTSPC * 3)            // 24 flats per finisher
#define NGRP    8                      // bc groups in finish stage A
#define BCG     (BC / NGRP)            // 16 bc per group

// Partial per-(n,c) stats: g_part[bc][stat][flat], stat: 0 sxp, 1 ssp, 2 sxg, 3 ssg, 4 cnt
__device__ float  g_part[BC * 5 * NF];      // 15.7 MB, fully overwritten each replay
__device__ float4 g_pscal[PCTA];            // per-CTA: cnt3x, recon, vels, velc3x
__device__ float  g_fin[RFIN];              // per-finisher identity partial
__device__ unsigned g_item;                 // work-stealing counter (self-reset)
__device__ unsigned g_done;                 // completed-CTA counter (self-reset)
__device__ unsigned g_fctr;                 // finisher counter (self-reset)

__global__ __launch_bounds__(THREADS, 8) void persist_k(
    const float* __restrict__ pred,
    const float* __restrict__ gt,
    const float* __restrict__ vis,
    float* __restrict__ out)
{
    const int tid = threadIdx.x;
    const int bid = blockIdx.x;

    __shared__ unsigned s_item;
    __shared__ __align__(16) float swarp[8][4];
    __shared__ __align__(16) float sgrp[NGRP][5][FLATSPC];   // float4-written: MUST be 16B aligned
    __shared__ __align__(16) float scomb[5][FLATSPC];
    __shared__ bool islast;

    // thread-level scalar accumulators, carried across items
    float acc_cnt = 0.f, acc_rec = 0.f, acc_vls = 0.f, acc_vlc = 0.f;

    // ===================== phase 1: work-stealing stream =====================
    for (;;) {
        if (tid == 0) s_item = atomicAdd(&g_item, 1u);
        __syncthreads();
        const unsigned it = s_item;
        __syncthreads();
        if (it >= NITEMS) break;

        const int bc     = it / WINDOWS;
        const int window = it - bc * WINDOWS;
        const int flat   = window * THREADS + tid;
        const int chunk  = bc & (NCHUNKS - 1);
        const int b      = bc >> 3;                // NCHUNKS = 8
        const int t0     = chunk * TCHUNK;

        const int   n = flat / 3;
        const int   c = flat - 3 * n;
        const float w = (c == 2) ? 2.f : 1.f;

        const int row0 = b * TT + t0;
        const float* pp = pred + (long)row0 * NF + flat;
        const float* gp = gt   + (long)row0 * NF + flat;
        const float* vp = vis  + (long)row0 * NPTS + n;

        float sxp = 0.f, ssp = 0.f, sxg = 0.f, ssg = 0.f, cnt = 0.f;
        float pd = 0.f, pm = 0.f;
        if (t0 > 0) {
            pm = (vp[-NPTS] > 0.5f) ? 1.f : 0.f;
            pd = pp[-NF] - gp[-NF];
        }

#pragma unroll 4
        for (int t = 0; t < TCHUNK; ++t) {
            float m = (vp[0] > 0.5f) ? 1.f : 0.f;
            float p = pp[0];
            float g = gp[0];
            pp += NF; gp += NF; vp += NPTS;

            float d = p - g;
            acc_rec += w * (m * d) * d;
            cnt     += m;

            float mp = m * p, mg = m * g;
            sxp += mp;  ssp += mp * p;
            sxg += mg;  ssg += mg * g;

            float vm = m * pm;
            float tv = d - pd;
            acc_vls += (vm * tv) * tv;
            acc_vlc += vm;

            pd = d; pm = m;
        }
        acc_cnt += cnt;

        // per-(n,c) stats -> partial buffer (coalesced stores, no atomics)
        float* o = &g_part[(long)bc * 5 * NF + flat];
        o[0 * NF] = sxp;
        o[1 * NF] = ssp;
        o[2 * NF] = sxg;
        o[3 * NF] = ssg;
        o[4 * NF] = cnt;
    }

    // CTA scalar reduce -> one float4, then signal done
    {
        const unsigned fmask = 0xffffffffu;
#pragma unroll
        for (int o = 16; o > 0; o >>= 1) {
            acc_cnt += __shfl_down_sync(fmask, acc_cnt, o);
            acc_rec += __shfl_down_sync(fmask, acc_rec, o);
            acc_vls += __shfl_down_sync(fmask, acc_vls, o);
            acc_vlc += __shfl_down_sync(fmask, acc_vlc, o);
        }
        int wd = tid >> 5;
        if ((tid & 31) == 0) {
            swarp[wd][0] = acc_cnt; swarp[wd][1] = acc_rec;
            swarp[wd][2] = acc_vls; swarp[wd][3] = acc_vlc;
        }
        __syncthreads();
        if (tid == 0) {
            float s0 = 0.f, s1 = 0.f, s2 = 0.f, s3 = 0.f;
#pragma unroll
            for (int i = 0; i < 8; ++i) {
                s0 += swarp[i][0]; s1 += swarp[i][1]; s2 += swarp[i][2]; s3 += swarp[i][3];
            }
            g_pscal[bid] = make_float4(s0, s1, s2, s3);
            __threadfence();                       // release partials + pscal
            atomicAdd(&g_done, 1u);
        }
    }

    if (bid >= RFIN) return;                       // non-finishers exit, free slots

    // ===================== phase 2: finishers (bounded wait) =================
    if (tid == 0) {
        volatile unsigned* dc = &g_done;
        while (*dc < PCTA) __nanosleep(64);
    }
    __syncthreads();
    __threadfence();

    const int fx = bid;
    const int f0 = fx * FLATSPC;

    // Stage A: 240 threads -> grp = t/30, pair = t%30 (stat = pair/6, col = pair%6)
    if (tid < NGRP * 30) {
        int grp  = tid / 30;
        int pair = tid - grp * 30;
        int stat = pair / 6;
        int col  = pair - stat * 6;
        const float* base = g_part + (long)(grp * BCG) * 5 * NF
                                   + (long)stat * NF + f0 + col * 4;
        float4 s = make_float4(0.f, 0.f, 0.f, 0.f);
#pragma unroll
        for (int i = 0; i < BCG; ++i) {
            float4 v = __ldcg((const float4*)(base + (long)i * 5 * NF));
            s.x += v.x; s.y += v.y; s.z += v.z; s.w += v.w;
        }
        *(float4*)&sgrp[grp][stat][col * 4] = s;
    }
    __syncthreads();

    // Stage B1: combine groups (120 threads)
    if (tid < 5 * FLATSPC) {
        int stat = tid / FLATSPC;
        int fo   = tid - stat * FLATSPC;
        float s = 0.f;
#pragma unroll
        for (int g = 0; g < NGRP; ++g)
            s += sgrp[g][stat][fo];
        scomb[stat][fo] = s;
    }
    __syncthreads();

    // Stage B2: identity for this finisher's 8 points
    float idp = 0.f;
    if (tid < PTSPC) {
        int fo = tid * 3;
        float cn = scomb[4][fo];
        if (cn > 1.f) {
            float inv_n  = 1.f / cn;
            float inv_n1 = 1.f / (cn - 1.f);
            float adsum = 0.f, vgsum = 0.f;
#pragma unroll
            for (int k = 0; k < 3; ++k) {
                float sp  = scomb[0][fo + k];
                float ssp = scomb[1][fo + k];
                float sg  = scomb[2][fo + k];
                float ssg = scomb[3][fo + k];
                float vp = (ssp - sp * sp * inv_n) * inv_n1;
                float vg = (ssg - sg * sg * inv_n) * inv_n1;
                adsum += fabsf(vp - vg);
                vgsum += vg;
            }
            idp = adsum / (vgsum + 1e-6f);
        }
    }
    if (tid < 32) {
#pragma unroll
        for (int o = 16; o > 0; o >>= 1)
            idp += __shfl_down_sync(0xffffffffu, idp, o);
        if (tid == 0) g_fin[fx] = idp;
    }
    __threadfence();
    if (tid == 0) {
        unsigned old = atomicAdd(&g_fctr, 1u);
        islast = (old == RFIN - 1);
    }
    __syncthreads();

    if (islast) {
        __threadfence();
        __shared__ __align__(16) float red[5][RFIN];
        {
            float a0 = __ldcg(&g_fin[tid]);
            float s0 = 0.f, s1 = 0.f, s2 = 0.f, s3 = 0.f;
            for (int i = tid; i < PCTA; i += THREADS) {
                float4 v = __ldcg(&g_pscal[i]);
                s0 += v.x; s1 += v.y; s2 += v.z; s3 += v.w;
            }
            red[0][tid] = a0;
            red[1][tid] = s0; red[2][tid] = s1; red[3][tid] = s2; red[4][tid] = s3;
        }
        __syncthreads();
#pragma unroll
        for (int s = RFIN / 2; s > 0; s >>= 1) {
            if (tid < s) {
#pragma unroll
                for (int k = 0; k < 5; ++k)
                    red[k][tid] += red[k][tid + s];
            }
            __syncthreads();
        }

        if (tid == 0) {
            float identity = red[0][0] / (float)NPTS;
            // counts accumulated once per coord (3x per point) -> exact /3
            float nv = red[1][0] / 3.0f;
            float rs = red[2][0];
            float vs = red[3][0];
            float vc = red[4][0] / 3.0f;
            float recon    = (nv > 0.f) ? rs / fmaxf(nv, 1.f) : 0.f;
            float temporal = (vc > 0.f) ? vs / fmaxf(vc, 1.f) : 0.f;

            // adaptive re-weighting (faithful to reference)
            float rl = recon, tl = temporal, il = identity;
            bool  all_pos = (rl > 0.f) && (tl > 0.f) && (il > 0.f);
            float maxc    = fmaxf(rl, fmaxf(tl, il));
            float target  = maxc / 3.f;
            float thresh  = 10.f * target;
            float rw = (all_pos && rl > thresh) ? 1.0f * target / fmaxf(rl, 1e-30f) : 1.0f;
            float tw = (all_pos && tl > thresh) ? 0.5f * target / fmaxf(tl, 1e-30f) : 0.5f;
            float iw = (all_pos && il > thresh) ? 0.1f * target / fmaxf(il, 1e-30f) : 0.1f;

            out[0] = rw * recon + tw * temporal + iw * identity;
            out[1] = recon;
            out[2] = temporal;
            out[3] = identity;

            // self-reset counters for the next graph replay
            g_item = 0u;
            g_done = 0u;
            g_fctr = 0u;
        }
    }
}

extern "C" void kernel_launch(void* const* d_in, const int* in_sizes, int n_in,
                              void* d_out, int out_size)
{
    const float* pred = (const float*)d_in[0];
    const float* gt   = (const float*)d_in[1];
    const float* vis  = (const float*)d_in[2];
    float* out = (float*)d_out;
    (void)in_sizes; (void)n_in; (void)out_size;

    persist_k<<<PCTA, THREADS>>>(pred, gt, vis, out);   // single persistent launch
}

// round 13
// speedup vs baseline: 1.4802x; 1.4010x over previous
#include <cuda_runtime.h>

// Problem shape (fixed by the dataset reference)
#define BB      16
#define TT      256
#define NPTS    2048
#define NF      (NPTS * 3)             // 6144 flat (point,coord) indices
#define TCHUNK  32
#define NCHUNKS (TT / TCHUNK)          // 8
#define BC      (BB * NCHUNKS)         // 128 groups
#define THREADS 256
#define CPB     (NF / THREADS)         // 24 flat windows
#define NCTA    (BC * CPB)             // 3072 main CTAs

// Global accumulators (zero at module load; finish_k re-zeroes after each use)
__device__ float  g_stats[5 * NF];          // stat-major: sxp, ssp, sxg, ssg, cnt
__device__ float4 g_pscal[NCTA];            // per-CTA: cnt3x, recon, vels, velc3x

__global__ __launch_bounds__(THREADS) void main_k(
    const float* __restrict__ pred,
    const float* __restrict__ gt,
    const float* __restrict__ vis)
{
    const int bid   = blockIdx.x;
    const int tid   = threadIdx.x;
    const int bc    = bid / CPB;
    const int sub   = bid - bc * CPB;
    const int flat  = sub * THREADS + tid;
    const int chunk = bc & (NCHUNKS - 1);
    const int b     = bc >> 3;                 // NCHUNKS = 8
    const int t0    = chunk * TCHUNK;

    const int   n = flat / 3;
    const int   c = flat - 3 * n;
    const float w = (c == 2) ? 2.f : 1.f;

    const int row0 = b * TT + t0;
    const float* pp = pred + (long)row0 * NF + flat;
    const float* gp = gt   + (long)row0 * NF + flat;
    const float* vp = vis  + (long)row0 * NPTS + n;

    float sxp = 0.f, ssp = 0.f, sxg = 0.f, ssg = 0.f, cnt = 0.f;
    float recon = 0.f, vels = 0.f, velc = 0.f;

    float pd = 0.f, pm = 0.f;
    if (t0 > 0) {
        pm = (__ldcs(vp - NPTS) > 0.5f) ? 1.f : 0.f;
        pd = __ldcs(pp - NF) - __ldcs(gp - NF);
    }

#pragma unroll 4
    for (int t = 0; t < TCHUNK; ++t) {
        float m = (__ldcs(vp) > 0.5f) ? 1.f : 0.f;
        float p = __ldcs(pp);
        float g = __ldcs(gp);
        pp += NF; gp += NF; vp += NPTS;

        float d = p - g;
        recon += w * (m * d) * d;
        cnt   += m;

        float mp = m * p, mg = m * g;
        sxp += mp;  ssp += mp * p;
        sxg += mg;  ssg += mg * g;

        float vm = m * pm;
        float tv = d - pd;
        vels += (vm * tv) * tv;
        velc += vm;

        pd = d; pm = m;
    }

    // per-(n,c) stats -> global accumulators: 5 coalesced REDG.32 per thread
    atomicAdd(&g_stats[0 * NF + flat], sxp);
    atomicAdd(&g_stats[1 * NF + flat], ssp);
    atomicAdd(&g_stats[2 * NF + flat], sxg);
    atomicAdd(&g_stats[3 * NF + flat], ssg);
    atomicAdd(&g_stats[4 * NF + flat], cnt);

    // scalar partials: warp reduce -> smem -> one float4 store per CTA (no atomics)
    const unsigned fmask = 0xffffffffu;
    __shared__ float swarp[8][4];
#pragma unroll
    for (int o = 16; o > 0; o >>= 1) {
        cnt   += __shfl_down_sync(fmask, cnt,   o);
        recon += __shfl_down_sync(fmask, recon, o);
        vels  += __shfl_down_sync(fmask, vels,  o);
        velc  += __shfl_down_sync(fmask, velc,  o);
    }
    int wd = tid >> 5;
    if ((tid & 31) == 0) {
        swarp[wd][0] = cnt; swarp[wd][1] = recon; swarp[wd][2] = vels; swarp[wd][3] = velc;
    }
    __syncthreads();
    if (tid == 0) {
        float s0 = 0.f, s1 = 0.f, s2 = 0.f, s3 = 0.f;
#pragma unroll
        for (int i = 0; i < 8; ++i) {
            s0 += swarp[i][0]; s1 += swarp[i][1]; s2 += swarp[i][2]; s3 += swarp[i][3];
        }
        g_pscal[bid] = make_float4(s0, s1, s2, s3);
    }
}

// Single-CTA finish: identity from L2-warm stats, scalar fold, output, self-clean.
__global__ __launch_bounds__(1024) void finish_k(float* __restrict__ out)
{
    const int tid = threadIdx.x;

    // identity per-point contributions (2 points per thread)
    float idp = 0.f;
#pragma unroll
    for (int n = tid; n < NPTS; n += 1024) {
        int fo = 3 * n;
        float cn = g_stats[4 * NF + fo];
        if (cn > 1.f) {
            float inv_n  = 1.f / cn;
            float inv_n1 = 1.f / (cn - 1.f);
            float adsum = 0.f, vgsum = 0.f;
#pragma unroll
            for (int k = 0; k < 3; ++k) {
                float sp  = g_stats[0 * NF + fo + k];
                float ssp = g_stats[1 * NF + fo + k];
                float sg  = g_stats[2 * NF + fo + k];
                float ssg = g_stats[3 * NF + fo + k];
                float vp = (ssp - sp * sp * inv_n) * inv_n1;
                float vg = (ssg - sg * sg * inv_n) * inv_n1;
                adsum += fabsf(vp - vg);
                vgsum += vg;
            }
            idp += adsum / (vgsum + 1e-6f);
        }
    }

    // fold per-CTA scalar partials (3 float4 per thread)
    float s0 = 0.f, s1 = 0.f, s2 = 0.f, s3 = 0.f;
#pragma unroll
    for (int i = tid; i < NCTA; i += 1024) {
        float4 v = g_pscal[i];
        s0 += v.x; s1 += v.y; s2 += v.z; s3 += v.w;
    }

    // block reduce 5 values: warp shuffle -> smem -> warp 0
    const unsigned fmask = 0xffffffffu;
#pragma unroll
    for (int o = 16; o > 0; o >>= 1) {
        idp += __shfl_down_sync(fmask, idp, o);
        s0  += __shfl_down_sync(fmask, s0,  o);
        s1  += __shfl_down_sync(fmask, s1,  o);
        s2  += __shfl_down_sync(fmask, s2,  o);
        s3  += __shfl_down_sync(fmask, s3,  o);
    }
    __shared__ float sred[32][5];
    int wd = tid >> 5;
    if ((tid & 31) == 0) {
        sred[wd][0] = idp; sred[wd][1] = s0; sred[wd][2] = s1;
        sred[wd][3] = s2;  sred[wd][4] = s3;
    }
    __syncthreads();

    // self-clean stats for the next graph replay (all 1024 threads)
    for (int i = tid; i < 5 * NF; i += 1024)
        g_stats[i] = 0.f;

    if (tid < 32) {
        float a = (tid < 32) ? 0.f : 0.f;
        float r0 = 0.f, r1 = 0.f, r2 = 0.f, r3 = 0.f, r4 = 0.f;
        if (tid < 32) {   // 32 warps
            r0 = sred[tid][0]; r1 = sred[tid][1]; r2 = sred[tid][2];
            r3 = sred[tid][3]; r4 = sred[tid][4];
        }
        (void)a;
#pragma unroll
        for (int o = 16; o > 0; o >>= 1) {
            r0 += __shfl_down_sync(fmask, r0, o);
            r1 += __shfl_down_sync(fmask, r1, o);
            r2 += __shfl_down_sync(fmask, r2, o);
            r3 += __shfl_down_sync(fmask, r3, o);
            r4 += __shfl_down_sync(fmask, r4, o);
        }
        if (tid == 0) {
            float identity = r0 / (float)NPTS;
            // counts accumulated once per coord (3x per point) -> exact /3
            float nv = r1 / 3.0f;
            float rs = r2;
            float vs = r3;
            float vc = r4 / 3.0f;
            float recon    = (nv > 0.f) ? rs / fmaxf(nv, 1.f) : 0.f;
            float temporal = (vc > 0.f) ? vs / fmaxf(vc, 1.f) : 0.f;

            // adaptive re-weighting (faithful to reference)
            float rl = recon, tl = temporal, il = identity;
            bool  all_pos = (rl > 0.f) && (tl > 0.f) && (il > 0.f);
            float maxc    = fmaxf(rl, fmaxf(tl, il));
            float target  = maxc / 3.f;
            float thresh  = 10.f * target;
            float rw = (all_pos && rl > thresh) ? 1.0f * target / fmaxf(rl, 1e-30f) : 1.0f;
            float tw = (all_pos && tl > thresh) ? 0.5f * target / fmaxf(tl, 1e-30f) : 0.5f;
            float iw = (all_pos && il > thresh) ? 0.1f * target / fmaxf(il, 1e-30f) : 0.1f;

            out[0] = rw * recon + tw * temporal + iw * identity;
            out[1] = recon;
            out[2] = temporal;
            out[3] = identity;
        }
    }
}

extern "C" void kernel_launch(void* const* d_in, const int* in_sizes, int n_in,
                              void* d_out, int out_size)
{
    const float* pred = (const float*)d_in[0];
    const float* gt   = (const float*)d_in[1];
    const float* vis  = (const float*)d_in[2];
    float* out = (float*)d_out;
    (void)in_sizes; (void)n_in; (void)out_size;

    main_k<<<NCTA, THREADS>>>(pred, gt, vis);   // 3072 blocks x 256
    finish_k<<<1, 1024>>>(out);                 // single-CTA tail
}